// round 16
// baseline (speedup 1.0000x reference)
#include <cuda_runtime.h>
#include <cuda_bf16.h>
#include <cstdint>

#define MAX_NODES 50000

// ---------------- device scratch ----------------
__device__ float g_agg[MAX_NODES * 128];
__device__ float g_eb1[128];                // b1e + u @ W1e[48:64]
__device__ float g_nb1[128];                // b1n + u @ W1n[144:160]
__device__ float g_esum[128];
__device__ float g_nsum[128];
__device__ int   g_is64;
// B operands pre-shuffled into mma.sync fragment order, H/L interleaved:
// [layer][((ks*8+np)*32+lane)*2 + {0:H,1:L}]
__device__ __align__(32) uint4 g_F[8][12 * 8 * 32 * 2];

// ---------------- helpers ----------------
// fast hi/lo bf16 split of a float pair: 2x cvt.rn.bf16x2 + exact bit reconstruction
__device__ __forceinline__ void cvt_pair(float v0, float v1, uint32_t& hw, uint32_t& lw) {
    asm("cvt.rn.bf16x2.f32 %0, %2, %1;" : "=r"(hw) : "f"(v0), "f"(v1));
    const float hf0 = __uint_as_float(hw << 16);
    const float hf1 = __uint_as_float(hw & 0xFFFF0000u);
    const float l0 = v0 - hf0, l1 = v1 - hf1;
    asm("cvt.rn.bf16x2.f32 %0, %2, %1;" : "=r"(lw) : "f"(l0), "f"(l1));
}
__device__ __forceinline__ void mma_bf16(float* c, const uint32_t* a, const uint32_t* b) {
    asm volatile(
        "mma.sync.aligned.m16n8k16.row.col.f32.bf16.bf16.f32 "
        "{%0,%1,%2,%3}, {%4,%5,%6,%7}, {%8,%9}, {%0,%1,%2,%3};"
        : "+f"(c[0]), "+f"(c[1]), "+f"(c[2]), "+f"(c[3])
        : "r"(a[0]), "r"(a[1]), "r"(a[2]), "r"(a[3]), "r"(b[0]), "r"(b[1]));
}
__device__ __forceinline__ void red2(float* addr, float v0, float v1) {
    asm volatile("red.global.add.v2.f32 [%0], {%1,%2};"
                 :: "l"(addr), "f"(v0), "f"(v1) : "memory");
}
__device__ __forceinline__ void pref_l2(const void* p) {
    asm volatile("prefetch.global.L2 [%0];" :: "l"(p));
}
__device__ __forceinline__ void stcs2(float* p, float v0, float v1) {
    asm volatile("st.global.cs.v2.f32 [%0], {%1,%2};"
                 :: "l"(p), "f"(v0), "f"(v1) : "memory");
}

// Direct A-fragment load: two source rows (p1: rows g, p2: rows g+8), 16 cols.
__device__ __forceinline__ void load_afrag(const float* p1, const float* p2, int t2,
                                           bool ok1, bool ok2,
                                           uint32_t ah[4], uint32_t al[4]) {
    float2 z = make_float2(0.f, 0.f);
    float2 v00 = ok1 ? *(const float2*)(p1 + t2)     : z;
    float2 v01 = ok1 ? *(const float2*)(p1 + 8 + t2) : z;
    float2 v10 = ok2 ? *(const float2*)(p2 + t2)     : z;
    float2 v11 = ok2 ? *(const float2*)(p2 + 8 + t2) : z;
    cvt_pair(v00.x, v00.y, ah[0], al[0]);
    cvt_pair(v10.x, v10.y, ah[1], al[1]);
    cvt_pair(v01.x, v01.y, ah[2], al[2]);
    cvt_pair(v11.x, v11.y, ah[3], al[3]);
}

// One emulated-fp32 layer in registers with 1-deep B prefetch.
// acc starts from the layer bias (broadcast per column pair) so no post-add is needed.
// acc += Ah*Bh + Ah*Bl + Al*Bh, 16 n-tiles, KS k-steps.
template <int KS>
__device__ __forceinline__ void layer_reg(const uint4* __restrict__ f,
                                          const uint32_t ah[][4], const uint32_t al[][4],
                                          float acc[16][4], int lane,
                                          const float* __restrict__ sBiasRow) {
    const uint4* p = f + lane * 2;
    const int t2 = (lane & 3) * 2;
#pragma unroll
    for (int nt = 0; nt < 16; nt++) {
        const float2 b = *(const float2*)(sBiasRow + nt * 8 + t2);
        acc[nt][0] = b.x; acc[nt][1] = b.y;
        acc[nt][2] = b.x; acc[nt][3] = b.y;
    }
    uint4 h4 = p[0], l4 = p[1];
#pragma unroll
    for (int i = 0; i < KS * 8; i++) {
        const int ks = i >> 3, np = i & 7;
        uint4 h4n = h4, l4n = l4;
        if (i + 1 < KS * 8) {
            h4n = p[(i + 1) * 64];
            l4n = p[(i + 1) * 64 + 1];
        }
        const uint32_t bh[4] = {h4.x, h4.y, h4.z, h4.w};
        const uint32_t bl[4] = {l4.x, l4.y, l4.z, l4.w};
        mma_bf16(acc[2 * np],     ah[ks], bh);
        mma_bf16(acc[2 * np + 1], ah[ks], bh + 2);
        mma_bf16(acc[2 * np],     ah[ks], bl);
        mma_bf16(acc[2 * np + 1], ah[ks], bl + 2);
        mma_bf16(acc[2 * np],     al[ks], bh);
        mma_bf16(acc[2 * np + 1], al[ks], bh + 2);
        h4 = h4n; l4 = l4n;
    }
}

// acc (C frag incl. bias, 16 n-tiles) -> relu -> hi/lo A frags for next layer (k=128).
__device__ __forceinline__ void cvt_reg(const float acc[16][4],
                                        uint32_t ah[][4], uint32_t al[][4]) {
#pragma unroll
    for (int nt = 0; nt < 16; nt++) {
        const float v0 = fmaxf(acc[nt][0], 0.f);
        const float v1 = fmaxf(acc[nt][1], 0.f);
        const float v2 = fmaxf(acc[nt][2], 0.f);
        const float v3 = fmaxf(acc[nt][3], 0.f);
        uint32_t h0, l0, h1, l1;
        cvt_pair(v0, v1, h0, l0);
        cvt_pair(v2, v3, h1, l1);
        const int ks = nt >> 1, o = (nt & 1) * 2;
        ah[ks][o] = h0; ah[ks][o + 1] = h1;
        al[ks][o] = l0; al[ks][o + 1] = l1;
    }
}

// ---------------- fused prep kernel ----------------
// blocks 0..95:  B-fragment build (s = bid/12, ks = bid%12)
// block 96:      bias folding + esum/nsum zero
// block 97:      edge_index dtype detect
// blocks 98-105: L2-prefetch global-MLP weights (331KB)
// blocks 106+:   zero g_agg (grid-stride over float4)
__global__ void prep_all(const float* w0, const float* w1, const float* w2, const float* w3,
                         const float* w4, const float* w5, const float* w6, const float* w7,
                         const float* __restrict__ u,
                         const float* __restrict__ b1e, const float* __restrict__ b1n,
                         const unsigned* __restrict__ eiu, int E, long long total4,
                         const float* wg1, const float* wg2, const float* wg3, const float* wg4) {
    const int bid = blockIdx.x;
    const int tid = threadIdx.x;
    if (bid < 96) {
        const float* ws[8] = {w0, w1, w2, w3, w4, w5, w6, w7};
        const int KS[8] = {3, 8, 8, 8, 9, 8, 8, 8};
        const int KR[8] = {48, 128, 128, 128, 144, 128, 128, 128};
        const int s = bid / 12, ks = bid % 12;
        if (ks >= KS[s]) return;
        const float* w = ws[s];
        const int kr = KR[s];
        const int np = tid >> 5, lane = tid & 31;
        const int t = lane & 3, gg = lane >> 2;
        const int kb = ks * 16 + 2 * t;
        uint32_t h[4], l[4];
#pragma unroll
        for (int r = 0; r < 4; r++) {
            const int n = (np * 2 + (r >> 1)) * 8 + gg;
            const int k = kb + (r & 1) * 8;
            const float v0 = (k < kr)     ? w[k * 128 + n]       : 0.f;
            const float v1 = (k + 1 < kr) ? w[(k + 1) * 128 + n] : 0.f;
            cvt_pair(v0, v1, h[r], l[r]);
        }
        const int idx = ((ks * 8 + np) * 32 + lane) * 2;
        g_F[s][idx]     = make_uint4(h[0], h[1], h[2], h[3]);
        g_F[s][idx + 1] = make_uint4(l[0], l[1], l[2], l[3]);
    } else if (bid == 96) {
        const int col = tid & 127, half = tid >> 7;
        const float* w = half ? w4 : w0;
        const int row0 = half ? 144 : 48;
        float s = half ? b1n[col] : b1e[col];
#pragma unroll
        for (int k = 0; k < 16; k++) s = fmaf(u[k], w[(row0 + k) * 128 + col], s);
        if (half) g_nb1[col] = s; else g_eb1[col] = s;
        if (tid < 128) { g_esum[tid] = 0.f; g_nsum[tid] = 0.f; }
    } else if (bid == 97) {
        if (tid == 0) g_is64 = 1;
        __syncthreads();
        const int n = E < 2048 ? E : 2048;
        bool nz = false;
        for (int i = tid; i < n; i += 256)
            if (eiu[2 * i + 1] != 0) nz = true;
        if (nz) g_is64 = 0;
    } else if (bid < 106) {
        const int slice = bid - 98;  // 0..7
        const int idx0 = slice * 256 + tid;
        for (int i = idx0; i < 1088; i += 2048) pref_l2(wg1 + i * 32);
        for (int i = idx0; i < 512; i += 2048) {
            pref_l2(wg2 + i * 32);
            pref_l2(wg3 + i * 32);
            pref_l2(wg4 + i * 32);
        }
    } else {
        long long i = (long long)(bid - 106) * blockDim.x + tid;
        const long long stride = (long long)(gridDim.x - 106) * blockDim.x;
        float4* p = (float4*)g_agg;
        const float4 z = make_float4(0.f, 0.f, 0.f, 0.f);
        for (; i < total4; i += stride) p[i] = z;
    }
}

// ---------------- edge kernel: 32 rows/block, 64 threads, 6 CTAs/SM ----------------
__global__ void __launch_bounds__(64, 6)
edge_kernel(const float* __restrict__ x, const float* __restrict__ ea,
            const void* __restrict__ ei,
            const float* __restrict__ b2, const float* __restrict__ b3,
            const float* __restrict__ b4,
            float* __restrict__ e_out, int N, int E) {
    __shared__ float sBias[4][128];
    __shared__ int sSrc[32], sDst[32];

    const int tid = threadIdx.x, wid = tid >> 5, lane = tid & 31;
    const int g = lane >> 2, t2 = (lane & 3) * 2;
    const int eBase = blockIdx.x * 32;
    const int is64 = g_is64;

    if (tid < 32) {
        int e = eBase + tid;
        int s = 0, d = 0;
        if (e < E) {
            if (is64) { const long long* q = (const long long*)ei; s = (int)q[e]; d = (int)q[E + e]; }
            else      { const int* q = (const int*)ei;             s = q[e];      d = q[E + e]; }
        }
        sSrc[tid] = s; sDst[tid] = d;
    }
    for (int i = tid; i < 128; i += 64) {
        sBias[0][i] = g_eb1[i];
        sBias[1][i] = b2[i];
        sBias[2][i] = b3[i];
        sBias[3][i] = b4[i];
    }
    __syncthreads();

    const int r1 = wid * 16 + g, r2 = r1 + 8;
    const int e1 = eBase + r1, e2 = eBase + r2;
    const bool ok1 = e1 < E, ok2 = e2 < E;
    const int s1 = sSrc[r1], s2 = sSrc[r2];
    const int d1 = sDst[r1], d2 = sDst[r2];

    // layer-1 A frags straight from global: ks0=ea, ks1=x[src], ks2=x[dst] (u in bias)
    uint32_t ah[8][4], al[8][4];
    load_afrag(ea + (long long)e1 * 16, ea + (long long)e2 * 16, t2, ok1, ok2, ah[0], al[0]);
    load_afrag(x + (long long)s1 * 16,  x + (long long)s2 * 16,  t2, ok1, ok2, ah[1], al[1]);
    load_afrag(x + (long long)d1 * 16,  x + (long long)d2 * 16,  t2, ok1, ok2, ah[2], al[2]);

    float acc[16][4];
    layer_reg<3>(g_F[0], ah, al, acc, lane, sBias[0]);
    cvt_reg(acc, ah, al);
    layer_reg<8>(g_F[1], ah, al, acc, lane, sBias[1]);
    cvt_reg(acc, ah, al);
    layer_reg<8>(g_F[2], ah, al, acc, lane, sBias[2]);
    cvt_reg(acc, ah, al);
    layer_reg<8>(g_F[3], ah, al, acc, lane, sBias[3]);

    // epilogue: streaming STG (evict-first; e_out is write-once) + vector atomics
#pragma unroll
    for (int nt = 0; nt < 16; nt++) {
        const int col = nt * 8 + t2;
        if (ok1) {
            stcs2(e_out + (long long)e1 * 128 + col, acc[nt][0], acc[nt][1]);
            red2(&g_agg[d1 * 128 + col], acc[nt][0], acc[nt][1]);
        }
        if (ok2) {
            stcs2(e_out + (long long)e2 * 128 + col, acc[nt][2], acc[nt][3]);
            red2(&g_agg[d2 * 128 + col], acc[nt][2], acc[nt][3]);
        }
    }
}

// ---------------- node kernel: 64 rows/block, 128 threads ----------------
__global__ void __launch_bounds__(128, 2)
node_kernel(const float* __restrict__ x,
            const float* __restrict__ b2, const float* __restrict__ b3,
            const float* __restrict__ b4,
            float* __restrict__ n_out, int N) {
    __shared__ float sBias[4][128];

    const int tid = threadIdx.x, wid = tid >> 5, lane = tid & 31;
    const int g = lane >> 2, t2 = (lane & 3) * 2;
    const int nBase = blockIdx.x * 64;
    const int lim = ((N - nBase) < 64) ? (N - nBase) : 64;

    if (tid < 128) {
        sBias[0][tid] = g_nb1[tid];
        sBias[1][tid] = b2[tid];
        sBias[2][tid] = b3[tid];
        sBias[3][tid] = b4[tid];
    }

    // esum contribution: column sums of this block's g_agg rows
    {
        float se = 0.f;
        for (int r = 0; r < lim; r++) se += g_agg[(long long)(nBase + r) * 128 + tid];
        atomicAdd(&g_esum[tid], se);
    }
    __syncthreads();

    const int r1 = wid * 16 + g, r2 = r1 + 8;
    const int n1 = nBase + r1, n2 = nBase + r2;
    const bool ok1 = n1 < N, ok2 = n2 < N;

    // layer-1 A frags straight from global: ks0=x, ks1-8=agg (K=144, u folded into bias)
    uint32_t ah[9][4], al[9][4];
    load_afrag(x + (long long)n1 * 16, x + (long long)n2 * 16, t2, ok1, ok2, ah[0], al[0]);
#pragma unroll
    for (int j = 0; j < 8; j++)
        load_afrag(g_agg + (long long)n1 * 128 + j * 16,
                   g_agg + (long long)n2 * 128 + j * 16, t2, ok1, ok2, ah[1 + j], al[1 + j]);

    float acc[16][4];
    layer_reg<9>(g_F[4], ah, al, acc, lane, sBias[0]);
    cvt_reg(acc, ah, al);
    layer_reg<8>(g_F[5], ah, al, acc, lane, sBias[1]);
    cvt_reg(acc, ah, al);
    layer_reg<8>(g_F[6], ah, al, acc, lane, sBias[2]);
    cvt_reg(acc, ah, al);
    layer_reg<8>(g_F[7], ah, al, acc, lane, sBias[3]);

#pragma unroll
    for (int nt = 0; nt < 16; nt++) {
        const int col = nt * 8 + t2;
        if (ok1)
            *(float2*)(n_out + (long long)n1 * 128 + col) = make_float2(acc[nt][0], acc[nt][1]);
        if (ok2)
            *(float2*)(n_out + (long long)n2 * 128 + col) = make_float2(acc[nt][2], acc[nt][3]);
    }

    // nsum contribution: re-read this block's n_out rows (L2-hot), column sums
    __syncthreads();
    {
        float sn = 0.f;
        for (int r = 0; r < lim; r++) sn += n_out[(long long)(nBase + r) * 128 + tid];
        atomicAdd(&g_nsum[tid], sn);
    }
}

// ---------------- global kernel: 1024 threads, 8-way K-split per column ----------------
__global__ void __launch_bounds__(1024)
global_kernel(const float* __restrict__ u,
              const float* __restrict__ w1, const float* __restrict__ b1,
              const float* __restrict__ w2, const float* __restrict__ b2,
              const float* __restrict__ w3, const float* __restrict__ b3,
              const float* __restrict__ w4, const float* __restrict__ b4,
              float* __restrict__ g_out) {
    __shared__ float sIn[272];
    __shared__ float sH[128];
    __shared__ float sPart[8][128];
    const int tid = threadIdx.x;
    const int col = tid & 127, part = tid >> 7;   // 8 K-slices per column

    // prefetch later layers while layer-1 runs
    for (int i = tid; i < 512; i += 1024) {
        pref_l2(w2 + i * 32);
        pref_l2(w3 + i * 32);
        pref_l2(w4 + i * 32);
    }

    if (tid < 16)                    sIn[tid] = u[tid];
    else if (tid < 144)              sIn[tid] = g_nsum[tid - 16];
    else if (tid < 272)              sIn[tid] = g_esum[tid - 144];
    __syncthreads();

    // layer 1: K=272 = 8 x 34
    {
        const int k0 = part * 34;
        float s = 0.f;
#pragma unroll
        for (int k = 0; k < 34; k++)
            s = fmaf(sIn[k0 + k], w1[(k0 + k) * 128 + col], s);
        sPart[part][col] = s;
    }
    __syncthreads();
    if (part == 0) {
        float a = b1[col];
#pragma unroll
        for (int p = 0; p < 8; p++) a += sPart[p][col];
        sH[col] = fmaxf(a, 0.f);
    }
    __syncthreads();

    // layers 2-4: K=128 = 8 x 16
    const float* ws[3] = {w2, w3, w4};
    const float* bs[3] = {b2, b3, b4};
#pragma unroll 1
    for (int l = 0; l < 3; l++) {
        const float* w = ws[l];
        const int k0 = part * 16;
        float s = 0.f;
#pragma unroll
        for (int k = 0; k < 16; k++)
            s = fmaf(sH[k0 + k], w[(k0 + k) * 128 + col], s);
        sPart[part][col] = s;
        __syncthreads();
        if (part == 0) {
            float a = bs[l][col];
#pragma unroll
            for (int p = 0; p < 8; p++) a += sPart[p][col];
            if (l < 2) sH[col] = fmaxf(a, 0.f);
            else       g_out[col] = a;
        }
        __syncthreads();
    }
}

// ---------------- host launcher ----------------
extern "C" void kernel_launch(void* const* d_in, const int* in_sizes, int n_in,
                              void* d_out, int out_size) {
    const float* x  = (const float*)d_in[0];
    const float* ea = (const float*)d_in[1];
    const float* u  = (const float*)d_in[2];
    const void*  ei = d_in[3];

    const int N = in_sizes[0] / 16;
    const int E = in_sizes[1] / 16;

    float* out   = (float*)d_out;
    float* e_out = out;
    float* n_out = out + (long long)E * 128;
    float* g_out = out + (long long)E * 128 + (long long)N * 128;

    prep_all<<<512, 256>>>(
        (const float*)d_in[4],  (const float*)d_in[6],
        (const float*)d_in[8],  (const float*)d_in[10],
        (const float*)d_in[12], (const float*)d_in[14],
        (const float*)d_in[16], (const float*)d_in[18],
        u, (const float*)d_in[5], (const float*)d_in[13],
        (const unsigned*)ei, E, (long long)N * 32,
        (const float*)d_in[20], (const float*)d_in[22],
        (const float*)d_in[24], (const float*)d_in[26]);
    edge_kernel<<<(E + 31) / 32, 64>>>(
        x, ea, ei,
        (const float*)d_in[7], (const float*)d_in[9], (const float*)d_in[11],
        e_out, N, E);
    node_kernel<<<(N + 63) / 64, 128>>>(
        x,
        (const float*)d_in[15], (const float*)d_in[17], (const float*)d_in[19],
        n_out, N);
    global_kernel<<<1, 1024>>>(
        u,
        (const float*)d_in[20], (const float*)d_in[21],
        (const float*)d_in[22], (const float*)d_in[23],
        (const float*)d_in[24], (const float*)d_in[25],
        (const float*)d_in[26], (const float*)d_in[27],
        g_out);
}

// round 17
// speedup vs baseline: 1.0291x; 1.0291x over previous
#include <cuda_runtime.h>
#include <cuda_bf16.h>
#include <cstdint>

#define MAX_NODES 50000

// ---------------- device scratch ----------------
__device__ float g_agg[MAX_NODES * 128];
__device__ float g_eb1[128];                // b1e + u @ W1e[48:64]
__device__ float g_nb1[128];                // b1n + u @ W1n[144:160]
__device__ float g_esum[128];
__device__ float g_nsum[128];
__device__ int   g_is64;
// B operands pre-shuffled into mma.sync fragment order, H/L interleaved:
// [layer][((ks*8+np)*32+lane)*2 + {0:H,1:L}]
__device__ __align__(32) uint4 g_F[8][12 * 8 * 32 * 2];

// ---------------- helpers ----------------
// fast hi/lo bf16 split of a float pair: 2x cvt.rn.bf16x2 + exact bit reconstruction
__device__ __forceinline__ void cvt_pair(float v0, float v1, uint32_t& hw, uint32_t& lw) {
    asm("cvt.rn.bf16x2.f32 %0, %2, %1;" : "=r"(hw) : "f"(v0), "f"(v1));
    const float hf0 = __uint_as_float(hw << 16);
    const float hf1 = __uint_as_float(hw & 0xFFFF0000u);
    const float l0 = v0 - hf0, l1 = v1 - hf1;
    asm("cvt.rn.bf16x2.f32 %0, %2, %1;" : "=r"(lw) : "f"(l0), "f"(l1));
}
__device__ __forceinline__ void mma_bf16(float* c, const uint32_t* a, const uint32_t* b) {
    asm volatile(
        "mma.sync.aligned.m16n8k16.row.col.f32.bf16.bf16.f32 "
        "{%0,%1,%2,%3}, {%4,%5,%6,%7}, {%8,%9}, {%0,%1,%2,%3};"
        : "+f"(c[0]), "+f"(c[1]), "+f"(c[2]), "+f"(c[3])
        : "r"(a[0]), "r"(a[1]), "r"(a[2]), "r"(a[3]), "r"(b[0]), "r"(b[1]));
}
__device__ __forceinline__ void red2(float* addr, float v0, float v1) {
    asm volatile("red.global.add.v2.f32 [%0], {%1,%2};"
                 :: "l"(addr), "f"(v0), "f"(v1) : "memory");
}
__device__ __forceinline__ void pref_l2(const void* p) {
    asm volatile("prefetch.global.L2 [%0];" :: "l"(p));
}
__device__ __forceinline__ void stcs2(float* p, float v0, float v1) {
    asm volatile("st.global.cs.v2.f32 [%0], {%1,%2};"
                 :: "l"(p), "f"(v0), "f"(v1) : "memory");
}

// Direct A-fragment load: two source rows (p1: rows g, p2: rows g+8), 16 cols.
__device__ __forceinline__ void load_afrag(const float* p1, const float* p2, int t2,
                                           bool ok1, bool ok2,
                                           uint32_t ah[4], uint32_t al[4]) {
    float2 z = make_float2(0.f, 0.f);
    float2 v00 = ok1 ? *(const float2*)(p1 + t2)     : z;
    float2 v01 = ok1 ? *(const float2*)(p1 + 8 + t2) : z;
    float2 v10 = ok2 ? *(const float2*)(p2 + t2)     : z;
    float2 v11 = ok2 ? *(const float2*)(p2 + 8 + t2) : z;
    cvt_pair(v00.x, v00.y, ah[0], al[0]);
    cvt_pair(v10.x, v10.y, ah[1], al[1]);
    cvt_pair(v01.x, v01.y, ah[2], al[2]);
    cvt_pair(v11.x, v11.y, ah[3], al[3]);
}

// One emulated-fp32 layer in registers with 1-deep B prefetch.
// acc starts from the layer bias (broadcast per column pair) so no post-add is needed.
// acc += Ah*Bh + Ah*Bl + Al*Bh, 16 n-tiles, KS k-steps.
template <int KS>
__device__ __forceinline__ void layer_reg(const uint4* __restrict__ f,
                                          const uint32_t ah[][4], const uint32_t al[][4],
                                          float acc[16][4], int lane,
                                          const float* __restrict__ sBiasRow) {
    const uint4* p = f + lane * 2;
    const int t2 = (lane & 3) * 2;
#pragma unroll
    for (int nt = 0; nt < 16; nt++) {
        const float2 b = *(const float2*)(sBiasRow + nt * 8 + t2);
        acc[nt][0] = b.x; acc[nt][1] = b.y;
        acc[nt][2] = b.x; acc[nt][3] = b.y;
    }
    uint4 h4 = p[0], l4 = p[1];
#pragma unroll
    for (int i = 0; i < KS * 8; i++) {
        const int ks = i >> 3, np = i & 7;
        uint4 h4n = h4, l4n = l4;
        if (i + 1 < KS * 8) {
            h4n = p[(i + 1) * 64];
            l4n = p[(i + 1) * 64 + 1];
        }
        const uint32_t bh[4] = {h4.x, h4.y, h4.z, h4.w};
        const uint32_t bl[4] = {l4.x, l4.y, l4.z, l4.w};
        mma_bf16(acc[2 * np],     ah[ks], bh);
        mma_bf16(acc[2 * np + 1], ah[ks], bh + 2);
        mma_bf16(acc[2 * np],     ah[ks], bl);
        mma_bf16(acc[2 * np + 1], ah[ks], bl + 2);
        mma_bf16(acc[2 * np],     al[ks], bh);
        mma_bf16(acc[2 * np + 1], al[ks], bh + 2);
        h4 = h4n; l4 = l4n;
    }
}

// acc (C frag incl. bias, 16 n-tiles) -> relu -> hi/lo A frags for next layer (k=128).
__device__ __forceinline__ void cvt_reg(const float acc[16][4],
                                        uint32_t ah[][4], uint32_t al[][4]) {
#pragma unroll
    for (int nt = 0; nt < 16; nt++) {
        const float v0 = fmaxf(acc[nt][0], 0.f);
        const float v1 = fmaxf(acc[nt][1], 0.f);
        const float v2 = fmaxf(acc[nt][2], 0.f);
        const float v3 = fmaxf(acc[nt][3], 0.f);
        uint32_t h0, l0, h1, l1;
        cvt_pair(v0, v1, h0, l0);
        cvt_pair(v2, v3, h1, l1);
        const int ks = nt >> 1, o = (nt & 1) * 2;
        ah[ks][o] = h0; ah[ks][o + 1] = h1;
        al[ks][o] = l0; al[ks][o + 1] = l1;
    }
}

// ---------------- fused prep kernel ----------------
// blocks 0..95:  B-fragment build (s = bid/12, ks = bid%12)
// block 96:      bias folding + esum/nsum zero
// block 97:      edge_index dtype detect
// blocks 98-105: L2-prefetch global-MLP weights (331KB)
// blocks 106+:   zero g_agg (grid-stride over float4)
__global__ void prep_all(const float* w0, const float* w1, const float* w2, const float* w3,
                         const float* w4, const float* w5, const float* w6, const float* w7,
                         const float* __restrict__ u,
                         const float* __restrict__ b1e, const float* __restrict__ b1n,
                         const unsigned* __restrict__ eiu, int E, long long total4,
                         const float* wg1, const float* wg2, const float* wg3, const float* wg4) {
    const int bid = blockIdx.x;
    const int tid = threadIdx.x;
    if (bid < 96) {
        const float* ws[8] = {w0, w1, w2, w3, w4, w5, w6, w7};
        const int KS[8] = {3, 8, 8, 8, 9, 8, 8, 8};
        const int KR[8] = {48, 128, 128, 128, 144, 128, 128, 128};
        const int s = bid / 12, ks = bid % 12;
        if (ks >= KS[s]) return;
        const float* w = ws[s];
        const int kr = KR[s];
        const int np = tid >> 5, lane = tid & 31;
        const int t = lane & 3, gg = lane >> 2;
        const int kb = ks * 16 + 2 * t;
        uint32_t h[4], l[4];
#pragma unroll
        for (int r = 0; r < 4; r++) {
            const int n = (np * 2 + (r >> 1)) * 8 + gg;
            const int k = kb + (r & 1) * 8;
            const float v0 = (k < kr)     ? w[k * 128 + n]       : 0.f;
            const float v1 = (k + 1 < kr) ? w[(k + 1) * 128 + n] : 0.f;
            cvt_pair(v0, v1, h[r], l[r]);
        }
        const int idx = ((ks * 8 + np) * 32 + lane) * 2;
        g_F[s][idx]     = make_uint4(h[0], h[1], h[2], h[3]);
        g_F[s][idx + 1] = make_uint4(l[0], l[1], l[2], l[3]);
    } else if (bid == 96) {
        const int col = tid & 127, half = tid >> 7;
        const float* w = half ? w4 : w0;
        const int row0 = half ? 144 : 48;
        float s = half ? b1n[col] : b1e[col];
#pragma unroll
        for (int k = 0; k < 16; k++) s = fmaf(u[k], w[(row0 + k) * 128 + col], s);
        if (half) g_nb1[col] = s; else g_eb1[col] = s;
        if (tid < 128) { g_esum[tid] = 0.f; g_nsum[tid] = 0.f; }
    } else if (bid == 97) {
        if (tid == 0) g_is64 = 1;
        __syncthreads();
        const int n = E < 2048 ? E : 2048;
        bool nz = false;
        for (int i = tid; i < n; i += 256)
            if (eiu[2 * i + 1] != 0) nz = true;
        if (nz) g_is64 = 0;
    } else if (bid < 106) {
        const int slice = bid - 98;  // 0..7
        const int idx0 = slice * 256 + tid;
        for (int i = idx0; i < 1088; i += 2048) pref_l2(wg1 + i * 32);
        for (int i = idx0; i < 512; i += 2048) {
            pref_l2(wg2 + i * 32);
            pref_l2(wg3 + i * 32);
            pref_l2(wg4 + i * 32);
        }
    } else {
        long long i = (long long)(bid - 106) * blockDim.x + tid;
        const long long stride = (long long)(gridDim.x - 106) * blockDim.x;
        float4* p = (float4*)g_agg;
        const float4 z = make_float4(0.f, 0.f, 0.f, 0.f);
        for (; i < total4; i += stride) p[i] = z;
    }
}

// ---------------- edge kernel: 64 rows/block, 128 threads, ~2.5KB smem ----------------
__global__ void __launch_bounds__(128, 3)
edge_kernel(const float* __restrict__ x, const float* __restrict__ ea,
            const void* __restrict__ ei,
            const float* __restrict__ b2, const float* __restrict__ b3,
            const float* __restrict__ b4,
            float* __restrict__ e_out, int N, int E) {
    __shared__ float sBias[4][128];
    __shared__ int sSrc[64], sDst[64];

    const int tid = threadIdx.x, wid = tid >> 5, lane = tid & 31;
    const int g = lane >> 2, t2 = (lane & 3) * 2;
    const int eBase = blockIdx.x * 64;
    const int is64 = g_is64;

    for (int i = tid; i < 64; i += 128) {
        int e = eBase + i;
        int s = 0, d = 0;
        if (e < E) {
            if (is64) { const long long* q = (const long long*)ei; s = (int)q[e]; d = (int)q[E + e]; }
            else      { const int* q = (const int*)ei;             s = q[e];      d = q[E + e]; }
        }
        sSrc[i] = s; sDst[i] = d;
    }
    if (tid < 128) {
        sBias[0][tid] = g_eb1[tid];
        sBias[1][tid] = b2[tid];
        sBias[2][tid] = b3[tid];
        sBias[3][tid] = b4[tid];
    }
    __syncthreads();

    const int r1 = wid * 16 + g, r2 = r1 + 8;
    const int e1 = eBase + r1, e2 = eBase + r2;
    const bool ok1 = e1 < E, ok2 = e2 < E;
    const int s1 = sSrc[r1], s2 = sSrc[r2];
    const int d1 = sDst[r1], d2 = sDst[r2];

    // layer-1 A frags straight from global: ks0=ea, ks1=x[src], ks2=x[dst] (u in bias)
    uint32_t ah[8][4], al[8][4];
    load_afrag(ea + (long long)e1 * 16, ea + (long long)e2 * 16, t2, ok1, ok2, ah[0], al[0]);
    load_afrag(x + (long long)s1 * 16,  x + (long long)s2 * 16,  t2, ok1, ok2, ah[1], al[1]);
    load_afrag(x + (long long)d1 * 16,  x + (long long)d2 * 16,  t2, ok1, ok2, ah[2], al[2]);

    float acc[16][4];
    layer_reg<3>(g_F[0], ah, al, acc, lane, sBias[0]);
    cvt_reg(acc, ah, al);
    layer_reg<8>(g_F[1], ah, al, acc, lane, sBias[1]);
    cvt_reg(acc, ah, al);
    layer_reg<8>(g_F[2], ah, al, acc, lane, sBias[2]);
    cvt_reg(acc, ah, al);
    layer_reg<8>(g_F[3], ah, al, acc, lane, sBias[3]);

    // epilogue: streaming STG for write-once e_out + vector segment-sum atomics
#pragma unroll
    for (int nt = 0; nt < 16; nt++) {
        const int col = nt * 8 + t2;
        if (ok1) {
            stcs2(e_out + (long long)e1 * 128 + col, acc[nt][0], acc[nt][1]);
            red2(&g_agg[d1 * 128 + col], acc[nt][0], acc[nt][1]);
        }
        if (ok2) {
            stcs2(e_out + (long long)e2 * 128 + col, acc[nt][2], acc[nt][3]);
            red2(&g_agg[d2 * 128 + col], acc[nt][2], acc[nt][3]);
        }
    }
}

// ---------------- node kernel: 64 rows/block, 128 threads ----------------
__global__ void __launch_bounds__(128, 2)
node_kernel(const float* __restrict__ x,
            const float* __restrict__ b2, const float* __restrict__ b3,
            const float* __restrict__ b4,
            float* __restrict__ n_out, int N) {
    __shared__ float sBias[4][128];

    const int tid = threadIdx.x, wid = tid >> 5, lane = tid & 31;
    const int g = lane >> 2, t2 = (lane & 3) * 2;
    const int nBase = blockIdx.x * 64;
    const int lim = ((N - nBase) < 64) ? (N - nBase) : 64;

    if (tid < 128) {
        sBias[0][tid] = g_nb1[tid];
        sBias[1][tid] = b2[tid];
        sBias[2][tid] = b3[tid];
        sBias[3][tid] = b4[tid];
    }

    // esum contribution: column sums of this block's g_agg rows
    {
        float se = 0.f;
        for (int r = 0; r < lim; r++) se += g_agg[(long long)(nBase + r) * 128 + tid];
        atomicAdd(&g_esum[tid], se);
    }
    __syncthreads();

    const int r1 = wid * 16 + g, r2 = r1 + 8;
    const int n1 = nBase + r1, n2 = nBase + r2;
    const bool ok1 = n1 < N, ok2 = n2 < N;

    // layer-1 A frags straight from global: ks0=x, ks1-8=agg (K=144, u folded into bias)
    uint32_t ah[9][4], al[9][4];
    load_afrag(x + (long long)n1 * 16, x + (long long)n2 * 16, t2, ok1, ok2, ah[0], al[0]);
#pragma unroll
    for (int j = 0; j < 8; j++)
        load_afrag(g_agg + (long long)n1 * 128 + j * 16,
                   g_agg + (long long)n2 * 128 + j * 16, t2, ok1, ok2, ah[1 + j], al[1 + j]);

    float acc[16][4];
    layer_reg<9>(g_F[4], ah, al, acc, lane, sBias[0]);
    cvt_reg(acc, ah, al);
    layer_reg<8>(g_F[5], ah, al, acc, lane, sBias[1]);
    cvt_reg(acc, ah, al);
    layer_reg<8>(g_F[6], ah, al, acc, lane, sBias[2]);
    cvt_reg(acc, ah, al);
    layer_reg<8>(g_F[7], ah, al, acc, lane, sBias[3]);

#pragma unroll
    for (int nt = 0; nt < 16; nt++) {
        const int col = nt * 8 + t2;
        if (ok1)
            *(float2*)(n_out + (long long)n1 * 128 + col) = make_float2(acc[nt][0], acc[nt][1]);
        if (ok2)
            *(float2*)(n_out + (long long)n2 * 128 + col) = make_float2(acc[nt][2], acc[nt][3]);
    }

    // nsum contribution: re-read this block's n_out rows (L2-hot), column sums
    __syncthreads();
    {
        float sn = 0.f;
        for (int r = 0; r < lim; r++) sn += n_out[(long long)(nBase + r) * 128 + tid];
        atomicAdd(&g_nsum[tid], sn);
    }
}

// ---------------- global kernel: 1024 threads, 8-way K-split per column ----------------
__global__ void __launch_bounds__(1024)
global_kernel(const float* __restrict__ u,
              const float* __restrict__ w1, const float* __restrict__ b1,
              const float* __restrict__ w2, const float* __restrict__ b2,
              const float* __restrict__ w3, const float* __restrict__ b3,
              const float* __restrict__ w4, const float* __restrict__ b4,
              float* __restrict__ g_out) {
    __shared__ float sIn[272];
    __shared__ float sH[128];
    __shared__ float sPart[8][128];
    const int tid = threadIdx.x;
    const int col = tid & 127, part = tid >> 7;   // 8 K-slices per column

    // prefetch later layers while layer-1 runs
    for (int i = tid; i < 512; i += 1024) {
        pref_l2(w2 + i * 32);
        pref_l2(w3 + i * 32);
        pref_l2(w4 + i * 32);
    }

    if (tid < 16)                    sIn[tid] = u[tid];
    else if (tid < 144)              sIn[tid] = g_nsum[tid - 16];
    else if (tid < 272)              sIn[tid] = g_esum[tid - 144];
    __syncthreads();

    // layer 1: K=272 = 8 x 34
    {
        const int k0 = part * 34;
        float s = 0.f;
#pragma unroll
        for (int k = 0; k < 34; k++)
            s = fmaf(sIn[k0 + k], w1[(k0 + k) * 128 + col], s);
        sPart[part][col] = s;
    }
    __syncthreads();
    if (part == 0) {
        float a = b1[col];
#pragma unroll
        for (int p = 0; p < 8; p++) a += sPart[p][col];
        sH[col] = fmaxf(a, 0.f);
    }
    __syncthreads();

    // layers 2-4: K=128 = 8 x 16
    const float* ws[3] = {w2, w3, w4};
    const float* bs[3] = {b2, b3, b4};
#pragma unroll 1
    for (int l = 0; l < 3; l++) {
        const float* w = ws[l];
        const int k0 = part * 16;
        float s = 0.f;
#pragma unroll
        for (int k = 0; k < 16; k++)
            s = fmaf(sH[k0 + k], w[(k0 + k) * 128 + col], s);
        sPart[part][col] = s;
        __syncthreads();
        if (part == 0) {
            float a = bs[l][col];
#pragma unroll
            for (int p = 0; p < 8; p++) a += sPart[p][col];
            if (l < 2) sH[col] = fmaxf(a, 0.f);
            else       g_out[col] = a;
        }
        __syncthreads();
    }
}

// ---------------- host launcher ----------------
extern "C" void kernel_launch(void* const* d_in, const int* in_sizes, int n_in,
                              void* d_out, int out_size) {
    const float* x  = (const float*)d_in[0];
    const float* ea = (const float*)d_in[1];
    const float* u  = (const float*)d_in[2];
    const void*  ei = d_in[3];

    const int N = in_sizes[0] / 16;
    const int E = in_sizes[1] / 16;

    float* out   = (float*)d_out;
    float* e_out = out;
    float* n_out = out + (long long)E * 128;
    float* g_out = out + (long long)E * 128 + (long long)N * 128;

    prep_all<<<512, 256>>>(
        (const float*)d_in[4],  (const float*)d_in[6],
        (const float*)d_in[8],  (const float*)d_in[10],
        (const float*)d_in[12], (const float*)d_in[14],
        (const float*)d_in[16], (const float*)d_in[18],
        u, (const float*)d_in[5], (const float*)d_in[13],
        (const unsigned*)ei, E, (long long)N * 32,
        (const float*)d_in[20], (const float*)d_in[22],
        (const float*)d_in[24], (const float*)d_in[26]);
    edge_kernel<<<(E + 63) / 64, 128>>>(
        x, ea, ei,
        (const float*)d_in[7], (const float*)d_in[9], (const float*)d_in[11],
        e_out, N, E);
    node_kernel<<<(N + 63) / 64, 128>>>(
        x,
        (const float*)d_in[15], (const float*)d_in[17], (const float*)d_in[19],
        n_out, N);
    global_kernel<<<1, 1024>>>(
        u,
        (const float*)d_in[20], (const float*)d_in[21],
        (const float*)d_in[22], (const float*)d_in[23],
        (const float*)d_in[24], (const float*)d_in[25],
        (const float*)d_in[26], (const float*)d_in[27],
        g_out);
}